// round 7
// baseline (speedup 1.0000x reference)
#include <cuda_runtime.h>
#include <cuda_fp16.h>
#include <math.h>

#define N_NODES 50000
#define N_EDGES 600000
#define E_TOTAL (N_EDGES + N_NODES)
#define HID 128
#define N_GRAPHS 64
#define SCAN_BLOCKS ((N_NODES + 1023) / 1024)   // 49

// ---------------- scratch ----------------
__device__ __half g_hh[N_NODES * HID];   // fp16 gather payload
__device__ float g_act[N_NODES * HID];   // layer activation (fp32, GEMM input)
__device__ float g_as[N_NODES];
__device__ float g_ad[N_NODES];
__device__ int   g_deg[N_NODES];         // real-edge in-degree (self-loop added arithmetically)
__device__ int   g_rowptr[N_NODES + 1];
__device__ int   g_cursor[N_NODES];
__device__ int   g_col[E_TOTAL];
__device__ int   g_bsum[64];

// ---------------- CSR build ----------------
__global__ void k_count(const int* __restrict__ ei) {
    int e = blockIdx.x * blockDim.x + threadIdx.x;
    if (e < N_EDGES) atomicAdd(&g_deg[ei[N_EDGES + e]], 1);
}

// per-block inclusive scan of (deg+1) via warp shfl + block totals
__global__ __launch_bounds__(1024) void k_scan1() {
    __shared__ int wsum[32];
    int tid = threadIdx.x;
    int lane = tid & 31;
    int wid = tid >> 5;
    int i = blockIdx.x * 1024 + tid;
    int v = (i < N_NODES) ? (g_deg[i] + 1) : 0;   // +1 self-loop
    int x = v;
    #pragma unroll
    for (int off = 1; off < 32; off <<= 1) {
        int t = __shfl_up_sync(0xffffffffu, x, off);
        if (lane >= off) x += t;
    }
    if (lane == 31) wsum[wid] = x;
    __syncthreads();
    if (wid == 0) {
        int y = wsum[lane];
        #pragma unroll
        for (int off = 1; off < 32; off <<= 1) {
            int t = __shfl_up_sync(0xffffffffu, y, off);
            if (lane >= off) y += t;
        }
        wsum[lane] = y;
    }
    __syncthreads();
    int incl = x + (wid ? wsum[wid - 1] : 0);
    if (i < N_NODES) g_rowptr[i + 1] = incl;
    if (tid == 1023) g_bsum[blockIdx.x] = incl;
}

// add block offsets; init cursor; set rowptr[0]
__global__ __launch_bounds__(256) void k_scan3() {
    __shared__ int s_off;
    int tid = threadIdx.x;
    int g = blockIdx.x >> 2;
    if (tid < 32) {
        int o = 0;
        for (int j = tid; j < g; j += 32) o += g_bsum[j];
        #pragma unroll
        for (int off = 16; off > 0; off >>= 1)
            o += __shfl_xor_sync(0xffffffffu, o, off);
        if (tid == 0) s_off = o;
    }
    __syncthreads();
    int i = blockIdx.x * 256 + tid;
    if (i == 0) g_rowptr[0] = 0;
    if (i < N_NODES) {
        int val = g_rowptr[i + 1] + s_off;
        g_rowptr[i + 1] = val;
        g_cursor[i] = val - (g_deg[i] + 1);
    }
}

__global__ void k_fill(const int* __restrict__ ei) {
    int idx = blockIdx.x * blockDim.x + threadIdx.x;
    if (idx < N_EDGES) {
        int src = ei[idx];
        int dst = ei[N_EDGES + idx];
        int pos = atomicAdd(&g_cursor[dst], 1);
        g_col[pos] = src;
    } else if (idx < E_TOTAL) {
        int node = idx - N_EDGES;
        int pos = atomicAdd(&g_cursor[node], 1);
        g_col[pos] = node;
    }
}

// ---------------- TF32 helpers ----------------
__device__ __forceinline__ unsigned f2tf(float f) {
    unsigned r;
    asm("cvt.rna.tf32.f32 %0, %1;" : "=r"(r) : "f"(f));
    return r;
}

__device__ __forceinline__ void mma_tf32(float* c, const unsigned* a, unsigned b0, unsigned b1) {
    asm volatile(
        "mma.sync.aligned.m16n8k8.row.col.f32.tf32.tf32.f32 "
        "{%0,%1,%2,%3}, {%4,%5,%6,%7}, {%8,%9}, {%0,%1,%2,%3};"
        : "+f"(c[0]), "+f"(c[1]), "+f"(c[2]), "+f"(c[3])
        : "r"(a[0]), "r"(a[1]), "r"(a[2]), "r"(a[3]), "r"(b0), "r"(b1));
}

// ---------------- GEMM (tensor core, 3xTF32) + fused alpha, fp16 h output ----------------
#define PA 132
#define PW 136

__global__ __launch_bounds__(256, 2) void k_gemm(const float* __restrict__ X,
                                                 const float* __restrict__ W,
                                                 const float* __restrict__ a_src,
                                                 const float* __restrict__ a_dst,
                                                 int use_x) {
    extern __shared__ float smem[];
    float* sA = smem;                              // [64][PA]
    float* sW = smem + 64 * PA;                    // [128][PW]
    float* salpha = smem + 64 * PA + 128 * PW;     // [64][2]

    const float* A = use_x ? X : g_act;
    int tid = threadIdx.x;
    int lane = tid & 31;
    int wid = tid >> 5;
    int row0 = blockIdx.x * 64;

    int rg = wid & 1;
    int cg = wid >> 1;
    int wr = rg * 32;
    int nc0 = cg * 32;

    if (tid < 128) salpha[tid] = 0.f;

    for (int i = tid; i < 128 * 32; i += 256) {
        int r = i >> 5, cq = i & 31;
        float4 v = reinterpret_cast<const float4*>(W)[r * 32 + cq];
        *reinterpret_cast<float4*>(&sW[r * PW + cq * 4]) = v;
    }
    for (int i = tid; i < 64 * 32; i += 256) {
        int r = i >> 5, cq = i & 31;
        int grow = row0 + r;
        float4 v = make_float4(0.f, 0.f, 0.f, 0.f);
        if (grow < N_NODES)
            v = reinterpret_cast<const float4*>(A)[grow * 32 + cq];
        *reinterpret_cast<float4*>(&sA[r * PA + cq * 4]) = v;
    }
    __syncthreads();

    int qr = lane >> 2;
    int qc = lane & 3;

    float c[2][4][4];
    #pragma unroll
    for (int f = 0; f < 2; f++)
        #pragma unroll
        for (int nt = 0; nt < 4; nt++) {
            c[f][nt][0] = 0.f; c[f][nt][1] = 0.f; c[f][nt][2] = 0.f; c[f][nt][3] = 0.f;
        }

    #pragma unroll 2
    for (int ks = 0; ks < 16; ks++) {
        int k0 = ks * 8;
        unsigned ah[2][4], al[2][4];
        #pragma unroll
        for (int f = 0; f < 2; f++) {
            int rbase = wr + f * 16;
            float af0 = sA[(rbase + qr) * PA + k0 + qc];
            float af1 = sA[(rbase + qr + 8) * PA + k0 + qc];
            float af2 = sA[(rbase + qr) * PA + k0 + qc + 4];
            float af3 = sA[(rbase + qr + 8) * PA + k0 + qc + 4];
            ah[f][0] = f2tf(af0); al[f][0] = f2tf(af0 - __uint_as_float(ah[f][0]));
            ah[f][1] = f2tf(af1); al[f][1] = f2tf(af1 - __uint_as_float(ah[f][1]));
            ah[f][2] = f2tf(af2); al[f][2] = f2tf(af2 - __uint_as_float(ah[f][2]));
            ah[f][3] = f2tf(af3); al[f][3] = f2tf(af3 - __uint_as_float(ah[f][3]));
        }
        #pragma unroll
        for (int nt = 0; nt < 4; nt++) {
            int n0 = nc0 + nt * 8;
            float b0f = sW[(k0 + qc) * PW + n0 + qr];
            float b1f = sW[(k0 + qc + 4) * PW + n0 + qr];
            unsigned bh0 = f2tf(b0f), bh1 = f2tf(b1f);
            unsigned bl0 = f2tf(b0f - __uint_as_float(bh0));
            unsigned bl1 = f2tf(b1f - __uint_as_float(bh1));
            #pragma unroll
            for (int f = 0; f < 2; f++) {
                mma_tf32(c[f][nt], ah[f], bh0, bh1);
                mma_tf32(c[f][nt], al[f], bh0, bh1);
                mma_tf32(c[f][nt], ah[f], bl0, bl1);
            }
        }
    }

    // epilogue: fp16 h store + fused alpha partial dots
    float als[4] = {0.f, 0.f, 0.f, 0.f};
    float ald[4] = {0.f, 0.f, 0.f, 0.f};
    __half2* hh2 = reinterpret_cast<__half2*>(g_hh);

    #pragma unroll
    for (int f = 0; f < 2; f++) {
        int r_lo = row0 + wr + f * 16 + qr;
        int r_hi = r_lo + 8;
        #pragma unroll
        for (int nt = 0; nt < 4; nt++) {
            int col0 = nc0 + nt * 8 + 2 * qc;
            float s0 = __ldg(&a_src[col0]), s1 = __ldg(&a_src[col0 + 1]);
            float d0 = __ldg(&a_dst[col0]), d1 = __ldg(&a_dst[col0 + 1]);
            float* cc = c[f][nt];
            als[f * 2 + 0] += cc[0] * s0 + cc[1] * s1;
            ald[f * 2 + 0] += cc[0] * d0 + cc[1] * d1;
            als[f * 2 + 1] += cc[2] * s0 + cc[3] * s1;
            ald[f * 2 + 1] += cc[2] * d0 + cc[3] * d1;
            if (r_lo < N_NODES)
                hh2[r_lo * 64 + (col0 >> 1)] = __floats2half2_rn(cc[0], cc[1]);
            if (r_hi < N_NODES)
                hh2[r_hi * 64 + (col0 >> 1)] = __floats2half2_rn(cc[2], cc[3]);
        }
    }
    #pragma unroll
    for (int j = 0; j < 4; j++) {
        als[j] += __shfl_xor_sync(0xffffffffu, als[j], 1);
        als[j] += __shfl_xor_sync(0xffffffffu, als[j], 2);
        ald[j] += __shfl_xor_sync(0xffffffffu, ald[j], 1);
        ald[j] += __shfl_xor_sync(0xffffffffu, ald[j], 2);
    }
    if (qc == 0) {
        #pragma unroll
        for (int f = 0; f < 2; f++) {
            int lr_lo = wr + f * 16 + qr;
            atomicAdd(&salpha[lr_lo * 2 + 0], als[f * 2 + 0]);
            atomicAdd(&salpha[lr_lo * 2 + 1], ald[f * 2 + 0]);
            atomicAdd(&salpha[(lr_lo + 8) * 2 + 0], als[f * 2 + 1]);
            atomicAdd(&salpha[(lr_lo + 8) * 2 + 1], ald[f * 2 + 1]);
        }
    }
    __syncthreads();
    if (tid < 64) {
        int grow = row0 + tid;
        if (grow < N_NODES) {
            g_as[grow] = salpha[tid * 2 + 0];
            g_ad[grow] = salpha[tid * 2 + 1];
        }
    }
}

// ---------------- aggregation: cached (src,v) in regs, shfl broadcast in gather ----------------
__global__ __launch_bounds__(256) void k_agg(const float* __restrict__ bias) {
    int w = (blockIdx.x * blockDim.x + threadIdx.x) >> 5;
    int lane = threadIdx.x & 31;
    if (w >= N_NODES) return;

    int beg = g_rowptr[w];
    int end = g_rowptr[w + 1];
    int deg = end - beg;
    float ad = g_ad[w];

    // pass 1: lane-strided; cache (src, v) for first 128 edges in registers
    float vloc[4];
    int   sloc[4];
    float m = -1e30f, ss = 0.f;
    int ncached = deg < 128 ? deg : 128;

    #pragma unroll
    for (int slot = 0; slot < 4; slot++) {
        int i = slot * 32 + lane;
        if (i < ncached) {
            int s = g_col[beg + i];
            float v = g_as[s] + ad;
            v = v > 0.f ? v : 0.2f * v;
            sloc[slot] = s;
            vloc[slot] = v;
            if (v > m) { ss = ss * __expf(m - v) + 1.f; m = v; }
            else       { ss += __expf(v - m); }
        }
    }
    for (int i = 128 + lane; i < deg; i += 32) {     // rare overflow
        int s = g_col[beg + i];
        float v = g_as[s] + ad;
        v = v > 0.f ? v : 0.2f * v;
        if (v > m) { ss = ss * __expf(m - v) + 1.f; m = v; }
        else       { ss += __expf(v - m); }
    }

    float M = m;
    #pragma unroll
    for (int off = 16; off > 0; off >>= 1)
        M = fmaxf(M, __shfl_xor_sync(0xffffffffu, M, off));
    float sc = ss * __expf(m - M);
    #pragma unroll
    for (int off = 16; off > 0; off >>= 1)
        sc += __shfl_xor_sync(0xffffffffu, sc, off);
    float inv = 1.f / (sc + 1e-16f);

    // pass 2: weighted gather; (src, v) via shfl — no per-edge memory loads
    float4 acc = make_float4(0.f, 0.f, 0.f, 0.f);
    const uint2* h2 = reinterpret_cast<const uint2*>(g_hh);

    #pragma unroll
    for (int cpos = 0; cpos < 4; cpos++) {
        int base = cpos * 32;
        if (base < deg) {
            int lim = deg - base; if (lim > 32) lim = 32;
            float vv = vloc[cpos];
            int   sv = sloc[cpos];
            int j = 0;
            #pragma unroll 1
            for (; j + 4 <= lim; j += 4) {
                float v0 = __shfl_sync(0xffffffffu, vv, j + 0);
                float v1 = __shfl_sync(0xffffffffu, vv, j + 1);
                float v2 = __shfl_sync(0xffffffffu, vv, j + 2);
                float v3 = __shfl_sync(0xffffffffu, vv, j + 3);
                int s0 = __shfl_sync(0xffffffffu, sv, j + 0);
                int s1 = __shfl_sync(0xffffffffu, sv, j + 1);
                int s2 = __shfl_sync(0xffffffffu, sv, j + 2);
                int s3 = __shfl_sync(0xffffffffu, sv, j + 3);
                float w0 = __expf(v0 - M) * inv, w1 = __expf(v1 - M) * inv;
                float w2 = __expf(v2 - M) * inv, w3 = __expf(v3 - M) * inv;
                uint2 r0 = h2[s0 * 32 + lane];
                uint2 r1 = h2[s1 * 32 + lane];
                uint2 r2 = h2[s2 * 32 + lane];
                uint2 r3 = h2[s3 * 32 + lane];
                float2 a0 = __half22float2(*reinterpret_cast<__half2*>(&r0.x));
                float2 b0 = __half22float2(*reinterpret_cast<__half2*>(&r0.y));
                float2 a1 = __half22float2(*reinterpret_cast<__half2*>(&r1.x));
                float2 b1 = __half22float2(*reinterpret_cast<__half2*>(&r1.y));
                float2 a2 = __half22float2(*reinterpret_cast<__half2*>(&r2.x));
                float2 b2 = __half22float2(*reinterpret_cast<__half2*>(&r2.y));
                float2 a3 = __half22float2(*reinterpret_cast<__half2*>(&r3.x));
                float2 b3 = __half22float2(*reinterpret_cast<__half2*>(&r3.y));
                acc.x += w0 * a0.x + w1 * a1.x + w2 * a2.x + w3 * a3.x;
                acc.y += w0 * a0.y + w1 * a1.y + w2 * a2.y + w3 * a3.y;
                acc.z += w0 * b0.x + w1 * b1.x + w2 * b2.x + w3 * b3.x;
                acc.w += w0 * b0.y + w1 * b1.y + w2 * b2.y + w3 * b3.y;
            }
            for (; j < lim; j++) {
                float v = __shfl_sync(0xffffffffu, vv, j);
                int s   = __shfl_sync(0xffffffffu, sv, j);
                float wgt = __expf(v - M) * inv;
                uint2 r = h2[s * 32 + lane];
                float2 a0 = __half22float2(*reinterpret_cast<__half2*>(&r.x));
                float2 b0 = __half22float2(*reinterpret_cast<__half2*>(&r.y));
                acc.x += wgt * a0.x;
                acc.y += wgt * a0.y;
                acc.z += wgt * b0.x;
                acc.w += wgt * b0.y;
            }
        }
    }
    // overflow (deg > 128): load from memory
    for (int e = beg + 128; e < end; e++) {
        int s = g_col[e];
        float v = g_as[s] + ad;
        v = v > 0.f ? v : 0.2f * v;
        float wgt = __expf(v - M) * inv;
        uint2 r = h2[s * 32 + lane];
        float2 a0 = __half22float2(*reinterpret_cast<__half2*>(&r.x));
        float2 b0 = __half22float2(*reinterpret_cast<__half2*>(&r.y));
        acc.x += wgt * a0.x;
        acc.y += wgt * a0.y;
        acc.z += wgt * b0.x;
        acc.w += wgt * b0.y;
    }

    float4 bb = reinterpret_cast<const float4*>(bias)[lane];
    acc.x += bb.x; acc.y += bb.y; acc.z += bb.z; acc.w += bb.w;
    acc.x = acc.x > 0.f ? acc.x : (__expf(acc.x) - 1.f);
    acc.y = acc.y > 0.f ? acc.y : (__expf(acc.y) - 1.f);
    acc.z = acc.z > 0.f ? acc.z : (__expf(acc.z) - 1.f);
    acc.w = acc.w > 0.f ? acc.w : (__expf(acc.w) - 1.f);

    reinterpret_cast<float4*>(g_act)[w * 32 + lane] = acc;
}

// ---------------- global mean pool ----------------
__global__ __launch_bounds__(512) void k_pool(const int* __restrict__ batch,
                                              float* __restrict__ out) {
    int g = blockIdx.x;
    int tid = threadIdx.x;
    int sub = tid >> 7;
    int d = tid & 127;

    int lo = 0, hi = N_NODES;
    while (lo < hi) { int mid = (lo + hi) >> 1; if (batch[mid] < g) lo = mid + 1; else hi = mid; }
    int start = lo;
    lo = 0; hi = N_NODES;
    while (lo < hi) { int mid = (lo + hi) >> 1; if (batch[mid] < g + 1) lo = mid + 1; else hi = mid; }
    int stop = lo;

    float s = 0.f;
    for (int i = start + sub; i < stop; i += 4)
        s += g_act[i * 128 + d];

    __shared__ float sm[4][128];
    sm[sub][d] = s;
    __syncthreads();
    if (sub == 0) {
        float tot = sm[0][d] + sm[1][d] + sm[2][d] + sm[3][d];
        int cnt = stop - start;
        out[g * 128 + d] = tot / (float)(cnt > 0 ? cnt : 1);
    }
}

// ---------------- launch ----------------
extern "C" void kernel_launch(void* const* d_in, const int* in_sizes, int n_in,
                              void* d_out, int out_size) {
    const float* x     = (const float*)d_in[0];
    const int*   ei    = (const int*)d_in[1];
    const int*   batch = (const int*)d_in[2];
    const float* W[3]   = { (const float*)d_in[3], (const float*)d_in[7],  (const float*)d_in[11] };
    const float* asr[3] = { (const float*)d_in[4], (const float*)d_in[8],  (const float*)d_in[12] };
    const float* ads[3] = { (const float*)d_in[5], (const float*)d_in[9],  (const float*)d_in[13] };
    const float* bs[3]  = { (const float*)d_in[6], (const float*)d_in[10], (const float*)d_in[14] };
    float* out = (float*)d_out;

    const int smem_bytes = (64 * PA + 128 * PW + 128) * (int)sizeof(float);
    cudaFuncSetAttribute(k_gemm, cudaFuncAttributeMaxDynamicSharedMemorySize, smem_bytes);

    // zero degree array via memset node (no init kernel)
    void* degp = nullptr;
    cudaGetSymbolAddress(&degp, g_deg);
    cudaMemsetAsync(degp, 0, N_NODES * sizeof(int));

    const int gemm_grid = (N_NODES + 63) / 64;
    const int warp_grid = (N_NODES * 32 + 255) / 256;

    // CSR prefix (gemm1 is CSR-independent; placed 4th so ncu profiles it)
    k_count<<<(N_EDGES + 255) / 256, 256>>>(ei);
    k_scan1<<<SCAN_BLOCKS, 1024>>>();
    k_scan3<<<(N_NODES + 255) / 256, 256>>>();
    k_gemm<<<gemm_grid, 256, smem_bytes>>>(x, W[0], asr[0], ads[0], 1);
    k_fill<<<(E_TOTAL + 255) / 256, 256>>>(ei);
    k_agg<<<warp_grid, 256>>>(bs[0]);

    for (int l = 1; l < 3; l++) {
        k_gemm<<<gemm_grid, 256, smem_bytes>>>(x, W[l], asr[l], ads[l], 0);
        k_agg<<<warp_grid, 256>>>(bs[l]);
    }

    k_pool<<<N_GRAPHS, 512>>>(batch, out);
}